// round 6
// baseline (speedup 1.0000x reference)
#include <cuda_runtime.h>

#define BATCH 64
#define H0 256
#define W0 256
#define H1 128
#define W1 128
#define NPIX0 (H0*W0)
#define NPIX1 (H1*W1)

typedef unsigned long long ull;

// ---- packed f32x2 helpers ----
__device__ __forceinline__ ull f2pack(float a, float b) {
    ull r; asm("mov.b64 %0, {%1, %2};" : "=l"(r) : "f"(a), "f"(b)); return r;
}
__device__ __forceinline__ void ffma2(ull& d, ull a, ull b) {
    asm("fma.rn.f32x2 %0, %1, %2, %0;" : "+l"(d) : "l"(a), "l"(b));
}
__device__ __forceinline__ float2 f2unpack(ull v) {
    float lo, hi; asm("mov.b64 {%0, %1}, %2;" : "=f"(lo), "=f"(hi) : "l"(v));
    return make_float2(lo, hi);
}

// ---------------- scratch (device globals: no allocations allowed) ----------
__device__ float g_t2[BATCH*16*NPIX1];    // conv2 out (67 MB)
__device__ float g_t3[BATCH*16*NPIX1];    // conv3 out (67 MB)
__device__ float g_part[BATCH*16*16];     // 32x32-block sums of fb (pool cells)
__device__ float g_phi[BATCH*3];          // combined head coefficients
__device__ float g_tmp[BATCH*NPIX0];      // horizontal blur intermediate (17 MB)

// =====================================================================
// Fused conv1 (3->16, 3x3, s1, SAME, relu) + conv2 (16->16, 3x3, s2,
// SAME pad_lo=0, relu). One block -> 16x16 conv2 output tile.
// =====================================================================
#define C12_SMEM_FLOATS (3*35*36 + 8*33*34 + 27*16 + 144*16 + 32)

__global__ void __launch_bounds__(256)
conv12_kernel(const float* __restrict__ x,
              const float* __restrict__ w1,
              const float* __restrict__ b1,
              const float* __restrict__ w2,
              const float* __restrict__ b2) {
    extern __shared__ float sm[];
    float* s_x   = sm;                     // [3][35][36]
    float* s_mid = s_x + 3*35*36;          // [8][33][34]
    float* s_w1  = s_mid + 8*33*34;        // [27][16]
    float* s_w2  = s_w1 + 27*16;           // [144][16]
    float* s_b1  = s_w2 + 144*16;          // [16]
    float* s_b2  = s_b1 + 16;              // [16]

    const int b = blockIdx.z;
    const int oy0 = blockIdx.y * 16, ox0 = blockIdx.x * 16;
    const int iy0 = oy0 * 2, ix0 = ox0 * 2;
    const int tid = threadIdx.y * 16 + threadIdx.x;
    const int ty = threadIdx.y, tx = threadIdx.x;
    const int lane = tid & 31, wrow = tid >> 5;   // 8 warps

    for (int i = tid; i < 27*16; i += 256) {
        int oc = i & 15, k = i >> 4;
        s_w1[k*16 + oc] = w1[oc*27 + k];
    }
    for (int i = tid; i < 144*16; i += 256) {
        int oc = i & 15, k = i >> 4;
        s_w2[k*16 + oc] = w2[oc*144 + k];
    }
    if (tid < 16) { s_b1[tid] = b1[tid]; s_b2[tid] = b2[tid]; }

    // x halo (3 x 35 x 35), warp-row / lane-col structure: no div, coalesced
    #pragma unroll
    for (int c = 0; c < 3; c++) {
        const float* src = &x[(b*3 + c)*NPIX0];
        float* dst = &s_x[c*35*36];
        for (int rr = wrow; rr < 35; rr += 8) {
            const int gy = iy0 + rr - 1;
            const bool yok = (gy >= 0) && (gy < H0);
            const float* srow = src + gy*W0;
            #pragma unroll
            for (int cc = lane; cc < 35; cc += 32) {
                const int gx = ix0 + cc - 1;
                float v = 0.f;
                if (yok && gx >= 0 && gx < W0) v = srow[gx];
                dst[rr*36 + cc] = v;
            }
        }
    }

    ull accp[8];      // conv2 accumulators: 16 oc as 8 packed pairs
    #pragma unroll
    for (int j = 0; j < 8; j++) accp[j] = 0ull;

    for (int occ = 0; occ < 16; occ += 8) {
        __syncthreads();
        // ---- conv1 for channels occ..occ+7 over 33x33 positions ----
        for (int i = tid; i < 33*33; i += 256) {
            // magic divide: yy = i/33 exact for i < 1089
            const int yy = (i * 1986) >> 16;
            const int xx = i - yy * 33;
            ull ap[4];
            #pragma unroll
            for (int j = 0; j < 4; j++)
                ap[j] = f2pack(s_b1[occ + 2*j], s_b1[occ + 2*j + 1]);
            #pragma unroll
            for (int c = 0; c < 3; c++)
                #pragma unroll
                for (int ky = 0; ky < 3; ky++)
                    #pragma unroll
                    for (int kx = 0; kx < 3; kx++) {
                        float v = s_x[(c*35 + yy + ky)*36 + xx + kx];
                        ull vb = f2pack(v, v);
                        const ull* wr = (const ull*)&s_w1[(c*9 + ky*3 + kx)*16 + occ];
                        #pragma unroll
                        for (int j = 0; j < 4; j++) ffma2(ap[j], vb, wr[j]);
                    }
            bool valid = (iy0 + yy < H0) && (ix0 + xx < W0);
            #pragma unroll
            for (int j = 0; j < 4; j++) {
                float2 a = f2unpack(ap[j]);
                s_mid[((2*j)*33 + yy)*34 + xx]   = valid ? fmaxf(a.x, 0.f) : 0.f;
                s_mid[((2*j+1)*33 + yy)*34 + xx] = valid ? fmaxf(a.y, 0.f) : 0.f;
            }
        }
        __syncthreads();
        // ---- conv2 partial accumulation over these 8 input channels ----
        #pragma unroll
        for (int c = 0; c < 8; c++)
            #pragma unroll
            for (int ky = 0; ky < 3; ky++)
                #pragma unroll
                for (int kx = 0; kx < 3; kx++) {
                    float v = s_mid[(c*33 + 2*ty + ky)*34 + 2*tx + kx];
                    ull vb = f2pack(v, v);
                    const ull* wr = (const ull*)&s_w2[((occ + c)*9 + ky*3 + kx)*16];
                    #pragma unroll
                    for (int j = 0; j < 8; j++) ffma2(accp[j], vb, wr[j]);
                }
    }

    const int oy = oy0 + ty, ox = ox0 + tx;
    #pragma unroll
    for (int j = 0; j < 8; j++) {
        float2 a = f2unpack(accp[j]);
        g_t2[((b*16 + 2*j)*H1 + oy)*W1 + ox]   = fmaxf(a.x + s_b2[2*j], 0.f);
        g_t2[((b*16 + 2*j+1)*H1 + oy)*W1 + ox] = fmaxf(a.y + s_b2[2*j+1], 0.f);
    }
}

// ---- shared halo loader for 128^2 16-channel tensors (34x34 halo) ----------
__device__ __forceinline__ void load_halo16(const float* __restrict__ src_base,
                                            float* __restrict__ s_in,
                                            int b, int oy0, int ox0,
                                            int lane, int wrow) {
    #pragma unroll 1
    for (int c = 0; c < 16; c++) {
        const float* src = src_base + (b*16 + c)*NPIX1;
        float* dst = &s_in[c*34*36];
        for (int rr = wrow; rr < 34; rr += 8) {
            const int gy = oy0 + rr - 1;
            const bool yok = (gy >= 0) && (gy < H1);
            const float* srow = src + gy*W1;
            #pragma unroll
            for (int cc = lane; cc < 34; cc += 32) {
                const int gx = ox0 + cc - 1;
                float v = 0.f;
                if (yok && gx >= 0 && gx < W1) v = srow[gx];
                dst[rr*36 + cc] = v;
            }
        }
    }
}

// =====================================================================
// conv3: 16->16, 3x3, s1, SAME, relu. 32x32 tile, 2x2 pixels per thread.
// =====================================================================
#define C3_SMEM_FLOATS (16*34*36 + 144*16 + 16)

__global__ void __launch_bounds__(256)
conv3_kernel(const float* __restrict__ w,
             const float* __restrict__ bias) {
    extern __shared__ float sm[];
    float* s_in = sm;                 // [16][34][36]
    float* s_w  = s_in + 16*34*36;    // [144][16]
    float* s_b  = s_w + 144*16;       // [16]

    const int b = blockIdx.z;
    const int oy0 = blockIdx.y * 32, ox0 = blockIdx.x * 32;
    const int tid = threadIdx.y * 16 + threadIdx.x;
    const int ty = threadIdx.y, tx = threadIdx.x;
    const int lane = tid & 31, wrow = tid >> 5;

    for (int i = tid; i < 144*16; i += 256) {
        int oc = i & 15, k = i >> 4;
        s_w[k*16 + oc] = w[oc*144 + k];
    }
    if (tid < 16) s_b[tid] = bias[tid];
    load_halo16(g_t2, s_in, b, oy0, ox0, lane, wrow);
    __syncthreads();

    ull acc0[8], acc1[8], acc2[8], acc3[8];
    #pragma unroll
    for (int j = 0; j < 8; j++) {
        ull bb = f2pack(s_b[2*j], s_b[2*j+1]);
        acc0[j] = bb; acc1[j] = bb; acc2[j] = bb; acc3[j] = bb;
    }

    #pragma unroll 2
    for (int c = 0; c < 16; c++) {
        const float* base = &s_in[(c*34)*36];
        #pragma unroll
        for (int ky = 0; ky < 3; ky++)
            #pragma unroll
            for (int kx = 0; kx < 3; kx++) {
                const ull* wr = (const ull*)&s_w[(c*9 + ky*3 + kx)*16];
                ull wq[8];
                #pragma unroll
                for (int j = 0; j < 8; j++) wq[j] = wr[j];
                const float* r0 = &base[(2*ty + ky)*36 + 2*tx + kx];
                ull v00 = f2pack(r0[0], r0[0]);
                ull v01 = f2pack(r0[1], r0[1]);
                ull v10 = f2pack(r0[36], r0[36]);
                ull v11 = f2pack(r0[37], r0[37]);
                #pragma unroll
                for (int j = 0; j < 8; j++) {
                    ffma2(acc0[j], v00, wq[j]);
                    ffma2(acc1[j], v01, wq[j]);
                    ffma2(acc2[j], v10, wq[j]);
                    ffma2(acc3[j], v11, wq[j]);
                }
            }
    }

    const int gy = oy0 + 2*ty, gx = ox0 + 2*tx;
    #pragma unroll
    for (int j = 0; j < 8; j++) {
        float2 a0 = f2unpack(acc0[j]), a1 = f2unpack(acc1[j]);
        float2 a2 = f2unpack(acc2[j]), a3 = f2unpack(acc3[j]);
        float* p0 = &g_t3[((b*16 + 2*j)*H1 + gy)*W1 + gx];
        *(float2*)p0        = make_float2(fmaxf(a0.x, 0.f), fmaxf(a1.x, 0.f));
        *(float2*)(p0 + W1) = make_float2(fmaxf(a2.x, 0.f), fmaxf(a3.x, 0.f));
        float* p1 = p0 + NPIX1;
        *(float2*)p1        = make_float2(fmaxf(a0.y, 0.f), fmaxf(a1.y, 0.f));
        *(float2*)(p1 + W1) = make_float2(fmaxf(a2.y, 0.f), fmaxf(a3.y, 0.f));
    }
}

// =====================================================================
// Fused depthwise 3x3 + relu + pointwise 1x1 + relu + 32x32 pool sum.
// =====================================================================
#define DW_SMEM_FLOATS (16*34*36 + 144 + 256 + 16 + 16 + 128)

__global__ void __launch_bounds__(256)
dwpw_kernel(const float* __restrict__ wd,
            const float* __restrict__ bd,
            const float* __restrict__ wp,
            const float* __restrict__ bp) {
    extern __shared__ float sm[];
    float* s_in  = sm;                  // [16][34][36]
    float* s_wd  = s_in + 16*34*36;     // [16][9]
    float* s_wp  = s_wd + 144;          // [16][16]  [ic][oc]
    float* s_bd  = s_wp + 256;          // [16]
    float* s_bp  = s_bd + 16;           // [16]
    float* s_red = s_bp + 16;           // [8][16]

    const int b = blockIdx.z;
    const int oy0 = blockIdx.y * 32, ox0 = blockIdx.x * 32;
    const int tid = threadIdx.y * 16 + threadIdx.x;
    const int ty = threadIdx.y, tx = threadIdx.x;
    const int lane = tid & 31, wrow = tid >> 5;

    if (tid < 144) s_wd[tid] = wd[tid];
    {
        int oc = tid >> 4, ic = tid & 15;
        s_wp[ic*16 + oc] = wp[oc*16 + ic];
    }
    if (tid < 16) { s_bd[tid] = bd[tid]; s_bp[tid] = bp[tid]; }
    load_halo16(g_t3, s_in, b, oy0, ox0, lane, wrow);
    __syncthreads();

    ull acc0[8], acc1[8], acc2[8], acc3[8];
    #pragma unroll
    for (int j = 0; j < 8; j++) {
        ull bb = f2pack(s_bp[2*j], s_bp[2*j+1]);
        acc0[j] = bb; acc1[j] = bb; acc2[j] = bb; acc3[j] = bb;
    }

    #pragma unroll 2
    for (int c = 0; c < 16; c++) {
        const float* base = &s_in[(c*34 + 2*ty)*36 + 2*tx];
        float vv[4][4];
        #pragma unroll
        for (int iy = 0; iy < 4; iy++)
            #pragma unroll
            for (int ix = 0; ix < 4; ix++)
                vv[iy][ix] = base[iy*36 + ix];
        ull d01 = f2pack(s_bd[c], s_bd[c]);
        ull d23 = d01;
        #pragma unroll
        for (int ky = 0; ky < 3; ky++)
            #pragma unroll
            for (int kx = 0; kx < 3; kx++) {
                float wvv = s_wd[c*9 + ky*3 + kx];
                ull wb = f2pack(wvv, wvv);
                ull va = f2pack(vv[ky][kx],   vv[ky][kx+1]);
                ull vb = f2pack(vv[ky+1][kx], vv[ky+1][kx+1]);
                ffma2(d01, va, wb);
                ffma2(d23, vb, wb);
            }
        float2 dab = f2unpack(d01), dcd = f2unpack(d23);
        float dw0 = fmaxf(dab.x, 0.f), dw1 = fmaxf(dab.y, 0.f);
        float dw2 = fmaxf(dcd.x, 0.f), dw3 = fmaxf(dcd.y, 0.f);
        ull p0 = f2pack(dw0, dw0), p1 = f2pack(dw1, dw1);
        ull p2 = f2pack(dw2, dw2), p3 = f2pack(dw3, dw3);
        const ull* wr = (const ull*)&s_wp[c*16];
        #pragma unroll
        for (int j = 0; j < 8; j++) {
            ull wq = wr[j];
            ffma2(acc0[j], p0, wq);
            ffma2(acc1[j], p1, wq);
            ffma2(acc2[j], p2, wq);
            ffma2(acc3[j], p3, wq);
        }
    }

    float t[16];
    #pragma unroll
    for (int j = 0; j < 8; j++) {
        float2 a0 = f2unpack(acc0[j]), a1 = f2unpack(acc1[j]);
        float2 a2 = f2unpack(acc2[j]), a3 = f2unpack(acc3[j]);
        t[2*j]   = fmaxf(a0.x,0.f) + fmaxf(a1.x,0.f) + fmaxf(a2.x,0.f) + fmaxf(a3.x,0.f);
        t[2*j+1] = fmaxf(a0.y,0.f) + fmaxf(a1.y,0.f) + fmaxf(a2.y,0.f) + fmaxf(a3.y,0.f);
    }
    #pragma unroll
    for (int oc = 0; oc < 16; oc++) {
        float v = t[oc];
        #pragma unroll
        for (int o = 16; o > 0; o >>= 1) v += __shfl_xor_sync(0xffffffffu, v, o);
        t[oc] = v;
    }
    const int warp = tid >> 5, ln = tid & 31;
    if (ln == 0) {
        #pragma unroll
        for (int oc = 0; oc < 16; oc++) s_red[warp*16 + oc] = t[oc];
    }
    __syncthreads();
    if (tid < 16) {
        float s = 0.f;
        #pragma unroll
        for (int w8 = 0; w8 < 8; w8++) s += s_red[w8*16 + tid];
        g_part[(b*16 + tid)*16 + blockIdx.y*4 + blockIdx.x] = s;
    }
}

// -------- combined head coefficients: phi = (phi1+phi2+phi3)/3 --------------
__global__ void phi_kernel(const float* __restrict__ wf1, const float* __restrict__ bf1,
                           const float* __restrict__ wf2, const float* __restrict__ bf2,
                           const float* __restrict__ wf3, const float* __restrict__ bf3) {
    const int b = blockIdx.x;
    const int t = threadIdx.x;
    const int c = t >> 4, ch = t & 15;
    __shared__ float red[48];
    float S = 0.f;
    if (t < 48) {
        const float* part = &g_part[(b*16 + ch)*16];
        float m[16];
        float sum16 = 0.f;
        #pragma unroll
        for (int p = 0; p < 16; p++) {
            m[p] = part[p] * (1.0f / 1024.0f);
            sum16 += m[p];
            S = fmaf(m[p], wf3[c*256 + ch*16 + p], S);
        }
        S = fmaf(sum16 * (1.f / 16.f), wf1[c*16 + ch], S);
        #pragma unroll
        for (int i = 0; i < 2; i++)
            #pragma unroll
            for (int j = 0; j < 2; j++) {
                float f2v = 0.25f * (m[(2*i)*4 + 2*j] + m[(2*i)*4 + 2*j + 1] +
                                     m[(2*i+1)*4 + 2*j] + m[(2*i+1)*4 + 2*j + 1]);
                S = fmaf(f2v, wf2[c*64 + ch*4 + i*2 + j], S);
            }
        red[t] = S;
    }
    __syncthreads();
    if (t < 3) {
        float tot = bf1[t] + bf2[t] + bf3[t];
        #pragma unroll
        for (int i = 0; i < 16; i++) tot += red[t*16 + i];
        g_phi[b*3 + t] = tot * (1.f / 3.f);
    }
}

// -------- fused grayscale + horizontal 21-tap Gaussian (reflect-101) --------
__global__ void grayblurh_kernel(const float* __restrict__ x, float* __restrict__ out) {
    __shared__ float row[256];
    __shared__ float sw[21];
    const int b = blockIdx.y, y = blockIdx.x;
    const int tx = threadIdx.x;
    if (tx < 21) {
        float t = (float)tx - 10.f;
        sw[tx] = expf(-(t * t) / 24.5f);
    }
    const float p0 = g_phi[b*3 + 0], p1 = g_phi[b*3 + 1], p2 = g_phi[b*3 + 2];
    const int i = y * 256 + tx;
    float v = p0 * x[(b*3 + 0)*NPIX0 + i]
            + p1 * x[(b*3 + 1)*NPIX0 + i]
            + p2 * x[(b*3 + 2)*NPIX0 + i];
    out[(b*3 + 1)*NPIX0 + i] = v;   // i_gray (channel 1)
    row[tx] = v;
    __syncthreads();
    float wsum = 0.f;
    #pragma unroll
    for (int t = 0; t < 21; t++) wsum += sw[t];
    float acc = 0.f;
    #pragma unroll
    for (int t = 0; t < 21; t++) {
        int xx = tx + t - 10;
        xx = xx < 0 ? -xx : (xx > 255 ? 510 - xx : xx);
        acc = fmaf(sw[t], row[xx], acc);
    }
    g_tmp[(b*256 + y)*256 + tx] = acc / wsum;
}

// -------- vertical 21-tap Gaussian + base/detail writes ---------------------
__global__ void blurv_kernel(float* __restrict__ out) {
    __shared__ float tile[84][32];
    __shared__ float sw[21];
    const int b = blockIdx.z;
    const int x0 = blockIdx.x * 32, y0 = blockIdx.y * 64;
    const int tid = threadIdx.y * 32 + threadIdx.x;
    if (tid < 21) {
        float t = (float)tid - 10.f;
        sw[tid] = expf(-(t * t) / 24.5f);
    }
    for (int i = tid; i < 84 * 32; i += 256) {
        int yy = i >> 5, xx = i & 31;
        int gy = y0 + yy - 10;
        gy = gy < 0 ? -gy : (gy > 255 ? 510 - gy : gy);
        tile[yy][xx] = g_tmp[(b*256 + gy)*256 + x0 + xx];
    }
    __syncthreads();
    float wsum = 0.f;
    #pragma unroll
    for (int t = 0; t < 21; t++) wsum += sw[t];
    const float inv = 1.f / wsum;
    const int tx = threadIdx.x;
    for (int r = 0; r < 8; r++) {
        const int ly = threadIdx.y * 8 + r;
        float acc = 0.f;
        #pragma unroll
        for (int t = 0; t < 21; t++) acc = fmaf(sw[t], tile[ly + t][tx], acc);
        const float base = acc * inv;
        const int gy = y0 + ly, gx = x0 + tx;
        const int idx = (b*3)*NPIX0 + gy*256 + gx;
        const float ig = out[idx + NPIX0];
        out[idx] = base;                  // base   (channel 0)
        out[idx + 2*NPIX0] = ig - base;   // detail (channel 2)
    }
}

// ---------------------------------------------------------------------------
extern "C" void kernel_launch(void* const* d_in, const int* in_sizes, int n_in,
                              void* d_out, int out_size) {
    const float* x   = (const float*)d_in[0];
    const float* w1  = (const float*)d_in[1];
    const float* b1  = (const float*)d_in[2];
    const float* w2  = (const float*)d_in[3];
    const float* b2  = (const float*)d_in[4];
    const float* w3  = (const float*)d_in[5];
    const float* b3  = (const float*)d_in[6];
    const float* wd  = (const float*)d_in[7];
    const float* bd  = (const float*)d_in[8];
    const float* wp  = (const float*)d_in[9];
    const float* bp  = (const float*)d_in[10];
    const float* wf1 = (const float*)d_in[11];
    const float* bf1 = (const float*)d_in[12];
    const float* wf2 = (const float*)d_in[13];
    const float* bf2 = (const float*)d_in[14];
    const float* wf3 = (const float*)d_in[15];
    const float* bf3 = (const float*)d_in[16];
    float* out = (float*)d_out;

    const int c12_smem = C12_SMEM_FLOATS * (int)sizeof(float);
    const int c3_smem  = C3_SMEM_FLOATS  * (int)sizeof(float);
    const int dw_smem  = DW_SMEM_FLOATS  * (int)sizeof(float);
    cudaFuncSetAttribute(conv12_kernel, cudaFuncAttributeMaxDynamicSharedMemorySize, c12_smem);
    cudaFuncSetAttribute(conv3_kernel,  cudaFuncAttributeMaxDynamicSharedMemorySize, c3_smem);
    cudaFuncSetAttribute(dwpw_kernel,   cudaFuncAttributeMaxDynamicSharedMemorySize, dw_smem);

    conv12_kernel<<<dim3(8, 8, BATCH), dim3(16, 16), c12_smem>>>(x, w1, b1, w2, b2);
    conv3_kernel<<<dim3(4, 4, BATCH), dim3(16, 16), c3_smem>>>(w3, b3);
    dwpw_kernel<<<dim3(4, 4, BATCH), dim3(16, 16), dw_smem>>>(wd, bd, wp, bp);
    phi_kernel<<<BATCH, 64>>>(wf1, bf1, wf2, bf2, wf3, bf3);
    grayblurh_kernel<<<dim3(256, BATCH), 256>>>(x, out);
    blurv_kernel<<<dim3(8, 4, BATCH), dim3(32, 8)>>>(out);
}

// round 9
// speedup vs baseline: 1.3965x; 1.3965x over previous
#include <cuda_runtime.h>

#define BATCH 64
#define H0 256
#define W0 256
#define H1 128
#define W1 128
#define NPIX0 (H0*W0)
#define NPIX1 (H1*W1)

typedef unsigned long long ull;

// ---- packed f32x2 helpers ----
__device__ __forceinline__ ull f2pack(float a, float b) {
    ull r; asm("mov.b64 %0, {%1, %2};" : "=l"(r) : "f"(a), "f"(b)); return r;
}
__device__ __forceinline__ void ffma2(ull& d, ull a, ull b) {
    asm("fma.rn.f32x2 %0, %1, %2, %0;" : "+l"(d) : "l"(a), "l"(b));
}
__device__ __forceinline__ float2 f2unpack(ull v) {
    float lo, hi; asm("mov.b64 {%0, %1}, %2;" : "=f"(lo), "=f"(hi) : "l"(v));
    return make_float2(lo, hi);
}

// ---------------- scratch (device globals: no allocations allowed) ----------
__device__ float g_t2[BATCH*16*NPIX1];    // conv2 out (67 MB)
__device__ float g_t3[BATCH*16*NPIX1];    // conv3 out (67 MB)
__device__ float g_part[BATCH*16*16];     // 32x32-block sums of fb (pool cells)
__device__ float g_phi[BATCH*3];          // combined head coefficients
__device__ float g_tmp[BATCH*NPIX0];      // horizontal blur intermediate (17 MB)

// =====================================================================
// Fused conv1 (3->16, 3x3, s1, SAME, relu) + conv2 (16->16, 3x3, s2,
// SAME pad_lo=0, relu). One block -> 16x16 conv2 output tile.
// =====================================================================
#define C12_SMEM_FLOATS (3*35*36 + 8*33*34 + 27*16 + 144*16 + 32)

__global__ void __launch_bounds__(256)
conv12_kernel(const float* __restrict__ x,
              const float* __restrict__ w1,
              const float* __restrict__ b1,
              const float* __restrict__ w2,
              const float* __restrict__ b2) {
    extern __shared__ float sm[];
    float* s_x   = sm;                     // [3][35][36]
    float* s_mid = s_x + 3*35*36;          // [8][33][34]
    float* s_w1  = s_mid + 8*33*34;        // [27][16]
    float* s_w2  = s_w1 + 27*16;           // [144][16]
    float* s_b1  = s_w2 + 144*16;          // [16]
    float* s_b2  = s_b1 + 16;              // [16]

    const int b = blockIdx.z;
    const int oy0 = blockIdx.y * 16, ox0 = blockIdx.x * 16;
    const int iy0 = oy0 * 2, ix0 = ox0 * 2;
    const int tid = threadIdx.y * 16 + threadIdx.x;
    const int ty = threadIdx.y, tx = threadIdx.x;

    for (int i = tid; i < 27*16; i += 256) {
        int oc = i & 15, k = i >> 4;
        s_w1[k*16 + oc] = w1[oc*27 + k];
    }
    for (int i = tid; i < 144*16; i += 256) {
        int oc = i & 15, k = i >> 4;
        s_w2[k*16 + oc] = w2[oc*144 + k];
    }
    if (tid < 16) { s_b1[tid] = b1[tid]; s_b2[tid] = b2[tid]; }

    for (int i = tid; i < 3*35*35; i += 256) {
        int c = i / 1225, r = i % 1225;
        int yy = r / 35, xx = r % 35;
        int gy = iy0 + yy - 1, gx = ix0 + xx - 1;
        float v = 0.f;
        if (gy >= 0 && gy < H0 && gx >= 0 && gx < W0)
            v = x[((b*3 + c)*H0 + gy)*W0 + gx];
        s_x[(c*35 + yy)*36 + xx] = v;
    }

    ull accp[8];      // conv2 accumulators: 16 oc as 8 packed pairs
    #pragma unroll
    for (int j = 0; j < 8; j++) accp[j] = 0ull;

    for (int occ = 0; occ < 16; occ += 8) {
        __syncthreads();
        // ---- conv1 for channels occ..occ+7 over 33x33 positions ----
        for (int i = tid; i < 33*33; i += 256) {
            const int yy = i / 33;
            const int xx = i - yy * 33;
            ull ap[4];
            #pragma unroll
            for (int j = 0; j < 4; j++)
                ap[j] = f2pack(s_b1[occ + 2*j], s_b1[occ + 2*j + 1]);
            #pragma unroll
            for (int c = 0; c < 3; c++)
                #pragma unroll
                for (int ky = 0; ky < 3; ky++)
                    #pragma unroll
                    for (int kx = 0; kx < 3; kx++) {
                        float v = s_x[(c*35 + yy + ky)*36 + xx + kx];
                        ull vb = f2pack(v, v);
                        const ulonglong2* wr2 = (const ulonglong2*)&s_w1[(c*9 + ky*3 + kx)*16 + occ];
                        ulonglong2 wa = wr2[0], wbq = wr2[1];
                        ffma2(ap[0], vb, wa.x);
                        ffma2(ap[1], vb, wa.y);
                        ffma2(ap[2], vb, wbq.x);
                        ffma2(ap[3], vb, wbq.y);
                    }
            bool valid = (iy0 + yy < H0) && (ix0 + xx < W0);
            #pragma unroll
            for (int j = 0; j < 4; j++) {
                float2 a = f2unpack(ap[j]);
                s_mid[((2*j)*33 + yy)*34 + xx]   = valid ? fmaxf(a.x, 0.f) : 0.f;
                s_mid[((2*j+1)*33 + yy)*34 + xx] = valid ? fmaxf(a.y, 0.f) : 0.f;
            }
        }
        __syncthreads();
        // ---- conv2 partial accumulation over these 8 input channels ----
        #pragma unroll
        for (int c = 0; c < 8; c++)
            #pragma unroll
            for (int ky = 0; ky < 3; ky++)
                #pragma unroll
                for (int kx = 0; kx < 3; kx++) {
                    float v = s_mid[(c*33 + 2*ty + ky)*34 + 2*tx + kx];
                    ull vb = f2pack(v, v);
                    const ulonglong2* wr2 = (const ulonglong2*)&s_w2[((occ + c)*9 + ky*3 + kx)*16];
                    ulonglong2 w0 = wr2[0], w1q = wr2[1], w2q = wr2[2], w3q = wr2[3];
                    ffma2(accp[0], vb, w0.x);
                    ffma2(accp[1], vb, w0.y);
                    ffma2(accp[2], vb, w1q.x);
                    ffma2(accp[3], vb, w1q.y);
                    ffma2(accp[4], vb, w2q.x);
                    ffma2(accp[5], vb, w2q.y);
                    ffma2(accp[6], vb, w3q.x);
                    ffma2(accp[7], vb, w3q.y);
                }
    }

    const int oy = oy0 + ty, ox = ox0 + tx;
    #pragma unroll
    for (int j = 0; j < 8; j++) {
        float2 a = f2unpack(accp[j]);
        g_t2[((b*16 + 2*j)*H1 + oy)*W1 + ox]   = fmaxf(a.x + s_b2[2*j], 0.f);
        g_t2[((b*16 + 2*j+1)*H1 + oy)*W1 + ox] = fmaxf(a.y + s_b2[2*j+1], 0.f);
    }
}

// =====================================================================
// conv3: 16->16, 3x3, s1, SAME, relu. 32x32 tile, 2x2 pixels per thread.
// Per c: 4x4 input patch via 8 LDS.64; weights via LDS.128.
// =====================================================================
#define C3_SMEM_FLOATS (16*34*36 + 144*16 + 16)

__global__ void __launch_bounds__(256)
conv3_kernel(const float* __restrict__ w,
             const float* __restrict__ bias) {
    extern __shared__ float sm[];
    float* s_in = sm;                 // [16][34][36]
    float* s_w  = s_in + 16*34*36;    // [144][16]
    float* s_b  = s_w + 144*16;       // [16]

    const int b = blockIdx.z;
    const int oy0 = blockIdx.y * 32, ox0 = blockIdx.x * 32;
    const int tid = threadIdx.y * 16 + threadIdx.x;
    const int ty = threadIdx.y, tx = threadIdx.x;

    for (int i = tid; i < 144*16; i += 256) {
        int oc = i & 15, k = i >> 4;
        s_w[k*16 + oc] = w[oc*144 + k];
    }
    if (tid < 16) s_b[tid] = bias[tid];
    for (int i = tid; i < 16*34*34; i += 256) {
        int c = i / 1156, r = i % 1156;
        int yy = r / 34, xx = r % 34;
        int gy = oy0 + yy - 1, gx = ox0 + xx - 1;
        float v = 0.f;
        if (gy >= 0 && gy < H1 && gx >= 0 && gx < W1)
            v = g_t2[((b*16 + c)*H1 + gy)*W1 + gx];
        s_in[(c*34 + yy)*36 + xx] = v;
    }
    __syncthreads();

    ull acc0[8], acc1[8], acc2[8], acc3[8];
    #pragma unroll
    for (int j = 0; j < 8; j++) {
        ull bb = f2pack(s_b[2*j], s_b[2*j+1]);
        acc0[j] = bb; acc1[j] = bb; acc2[j] = bb; acc3[j] = bb;
    }

    #pragma unroll 2
    for (int c = 0; c < 16; c++) {
        // 4x4 patch for the 2x2 output quad, via aligned float2 loads
        const float* base = &s_in[(c*34 + 2*ty)*36 + 2*tx];
        float vv[4][4];
        #pragma unroll
        for (int iy = 0; iy < 4; iy++) {
            float2 qa = *(const float2*)&base[iy*36];
            float2 qb = *(const float2*)&base[iy*36 + 2];
            vv[iy][0] = qa.x; vv[iy][1] = qa.y; vv[iy][2] = qb.x; vv[iy][3] = qb.y;
        }
        #pragma unroll
        for (int ky = 0; ky < 3; ky++)
            #pragma unroll
            for (int kx = 0; kx < 3; kx++) {
                const ulonglong2* wr2 = (const ulonglong2*)&s_w[(c*9 + ky*3 + kx)*16];
                ulonglong2 w0 = wr2[0], w1q = wr2[1], w2q = wr2[2], w3q = wr2[3];
                ull v00 = f2pack(vv[ky][kx],     vv[ky][kx]);
                ull v01 = f2pack(vv[ky][kx+1],   vv[ky][kx+1]);
                ull v10 = f2pack(vv[ky+1][kx],   vv[ky+1][kx]);
                ull v11 = f2pack(vv[ky+1][kx+1], vv[ky+1][kx+1]);
                ffma2(acc0[0], v00, w0.x); ffma2(acc0[1], v00, w0.y);
                ffma2(acc0[2], v00, w1q.x); ffma2(acc0[3], v00, w1q.y);
                ffma2(acc0[4], v00, w2q.x); ffma2(acc0[5], v00, w2q.y);
                ffma2(acc0[6], v00, w3q.x); ffma2(acc0[7], v00, w3q.y);
                ffma2(acc1[0], v01, w0.x); ffma2(acc1[1], v01, w0.y);
                ffma2(acc1[2], v01, w1q.x); ffma2(acc1[3], v01, w1q.y);
                ffma2(acc1[4], v01, w2q.x); ffma2(acc1[5], v01, w2q.y);
                ffma2(acc1[6], v01, w3q.x); ffma2(acc1[7], v01, w3q.y);
                ffma2(acc2[0], v10, w0.x); ffma2(acc2[1], v10, w0.y);
                ffma2(acc2[2], v10, w1q.x); ffma2(acc2[3], v10, w1q.y);
                ffma2(acc2[4], v10, w2q.x); ffma2(acc2[5], v10, w2q.y);
                ffma2(acc2[6], v10, w3q.x); ffma2(acc2[7], v10, w3q.y);
                ffma2(acc3[0], v11, w0.x); ffma2(acc3[1], v11, w0.y);
                ffma2(acc3[2], v11, w1q.x); ffma2(acc3[3], v11, w1q.y);
                ffma2(acc3[4], v11, w2q.x); ffma2(acc3[5], v11, w2q.y);
                ffma2(acc3[6], v11, w3q.x); ffma2(acc3[7], v11, w3q.y);
            }
    }

    const int gy = oy0 + 2*ty, gx = ox0 + 2*tx;
    #pragma unroll
    for (int j = 0; j < 8; j++) {
        float2 a0 = f2unpack(acc0[j]), a1 = f2unpack(acc1[j]);
        float2 a2 = f2unpack(acc2[j]), a3 = f2unpack(acc3[j]);
        float* p0 = &g_t3[((b*16 + 2*j)*H1 + gy)*W1 + gx];
        *(float2*)p0        = make_float2(fmaxf(a0.x, 0.f), fmaxf(a1.x, 0.f));
        *(float2*)(p0 + W1) = make_float2(fmaxf(a2.x, 0.f), fmaxf(a3.x, 0.f));
        float* p1 = p0 + NPIX1;
        *(float2*)p1        = make_float2(fmaxf(a0.y, 0.f), fmaxf(a1.y, 0.f));
        *(float2*)(p1 + W1) = make_float2(fmaxf(a2.y, 0.f), fmaxf(a3.y, 0.f));
    }
}

// =====================================================================
// Fused depthwise 3x3 + relu + pointwise 1x1 + relu + 32x32 pool sum.
// =====================================================================
#define DW_SMEM_FLOATS (16*34*36 + 144 + 256 + 16 + 16 + 128)

__global__ void __launch_bounds__(256)
dwpw_kernel(const float* __restrict__ wd,
            const float* __restrict__ bd,
            const float* __restrict__ wp,
            const float* __restrict__ bp) {
    extern __shared__ float sm[];
    float* s_in  = sm;                  // [16][34][36]
    float* s_wd  = s_in + 16*34*36;     // [16][9]
    float* s_wp  = s_wd + 144;          // [16][16]  [ic][oc]
    float* s_bd  = s_wp + 256;          // [16]
    float* s_bp  = s_bd + 16;           // [16]
    float* s_red = s_bp + 16;           // [8][16]

    const int b = blockIdx.z;
    const int oy0 = blockIdx.y * 32, ox0 = blockIdx.x * 32;
    const int tid = threadIdx.y * 16 + threadIdx.x;
    const int ty = threadIdx.y, tx = threadIdx.x;

    if (tid < 144) s_wd[tid] = wd[tid];
    {
        int oc = tid >> 4, ic = tid & 15;
        s_wp[ic*16 + oc] = wp[oc*16 + ic];
    }
    if (tid < 16) { s_bd[tid] = bd[tid]; s_bp[tid] = bp[tid]; }
    for (int i = tid; i < 16*34*34; i += 256) {
        int c = i / 1156, r = i % 1156;
        int yy = r / 34, xx = r % 34;
        int gy = oy0 + yy - 1, gx = ox0 + xx - 1;
        float v = 0.f;
        if (gy >= 0 && gy < H1 && gx >= 0 && gx < W1)
            v = g_t3[((b*16 + c)*H1 + gy)*W1 + gx];
        s_in[(c*34 + yy)*36 + xx] = v;
    }
    __syncthreads();

    ull acc0[8], acc1[8], acc2[8], acc3[8];
    #pragma unroll
    for (int j = 0; j < 8; j++) {
        ull bb = f2pack(s_bp[2*j], s_bp[2*j+1]);
        acc0[j] = bb; acc1[j] = bb; acc2[j] = bb; acc3[j] = bb;
    }

    #pragma unroll 2
    for (int c = 0; c < 16; c++) {
        const float* base = &s_in[(c*34 + 2*ty)*36 + 2*tx];
        float vv[4][4];
        #pragma unroll
        for (int iy = 0; iy < 4; iy++) {
            float2 qa = *(const float2*)&base[iy*36];
            float2 qb = *(const float2*)&base[iy*36 + 2];
            vv[iy][0] = qa.x; vv[iy][1] = qa.y; vv[iy][2] = qb.x; vv[iy][3] = qb.y;
        }
        ull d01 = f2pack(s_bd[c], s_bd[c]);
        ull d23 = d01;
        #pragma unroll
        for (int ky = 0; ky < 3; ky++)
            #pragma unroll
            for (int kx = 0; kx < 3; kx++) {
                float wvv = s_wd[c*9 + ky*3 + kx];
                ull wb = f2pack(wvv, wvv);
                ull va = f2pack(vv[ky][kx],   vv[ky][kx+1]);
                ull vb = f2pack(vv[ky+1][kx], vv[ky+1][kx+1]);
                ffma2(d01, va, wb);
                ffma2(d23, vb, wb);
            }
        float2 dab = f2unpack(d01), dcd = f2unpack(d23);
        float dw0 = fmaxf(dab.x, 0.f), dw1 = fmaxf(dab.y, 0.f);
        float dw2 = fmaxf(dcd.x, 0.f), dw3 = fmaxf(dcd.y, 0.f);
        ull p0 = f2pack(dw0, dw0), p1 = f2pack(dw1, dw1);
        ull p2 = f2pack(dw2, dw2), p3 = f2pack(dw3, dw3);
        const ulonglong2* wr2 = (const ulonglong2*)&s_wp[c*16];
        ulonglong2 w0 = wr2[0], w1q = wr2[1], w2q = wr2[2], w3q = wr2[3];
        ffma2(acc0[0], p0, w0.x); ffma2(acc0[1], p0, w0.y);
        ffma2(acc0[2], p0, w1q.x); ffma2(acc0[3], p0, w1q.y);
        ffma2(acc0[4], p0, w2q.x); ffma2(acc0[5], p0, w2q.y);
        ffma2(acc0[6], p0, w3q.x); ffma2(acc0[7], p0, w3q.y);
        ffma2(acc1[0], p1, w0.x); ffma2(acc1[1], p1, w0.y);
        ffma2(acc1[2], p1, w1q.x); ffma2(acc1[3], p1, w1q.y);
        ffma2(acc1[4], p1, w2q.x); ffma2(acc1[5], p1, w2q.y);
        ffma2(acc1[6], p1, w3q.x); ffma2(acc1[7], p1, w3q.y);
        ffma2(acc2[0], p2, w0.x); ffma2(acc2[1], p2, w0.y);
        ffma2(acc2[2], p2, w1q.x); ffma2(acc2[3], p2, w1q.y);
        ffma2(acc2[4], p2, w2q.x); ffma2(acc2[5], p2, w2q.y);
        ffma2(acc2[6], p2, w3q.x); ffma2(acc2[7], p2, w3q.y);
        ffma2(acc3[0], p3, w0.x); ffma2(acc3[1], p3, w0.y);
        ffma2(acc3[2], p3, w1q.x); ffma2(acc3[3], p3, w1q.y);
        ffma2(acc3[4], p3, w2q.x); ffma2(acc3[5], p3, w2q.y);
        ffma2(acc3[6], p3, w3q.x); ffma2(acc3[7], p3, w3q.y);
    }

    float t[16];
    #pragma unroll
    for (int j = 0; j < 8; j++) {
        float2 a0 = f2unpack(acc0[j]), a1 = f2unpack(acc1[j]);
        float2 a2 = f2unpack(acc2[j]), a3 = f2unpack(acc3[j]);
        t[2*j]   = fmaxf(a0.x,0.f) + fmaxf(a1.x,0.f) + fmaxf(a2.x,0.f) + fmaxf(a3.x,0.f);
        t[2*j+1] = fmaxf(a0.y,0.f) + fmaxf(a1.y,0.f) + fmaxf(a2.y,0.f) + fmaxf(a3.y,0.f);
    }
    #pragma unroll
    for (int oc = 0; oc < 16; oc++) {
        float v = t[oc];
        #pragma unroll
        for (int o = 16; o > 0; o >>= 1) v += __shfl_xor_sync(0xffffffffu, v, o);
        t[oc] = v;
    }
    const int warp = tid >> 5, lane = tid & 31;
    if (lane == 0) {
        #pragma unroll
        for (int oc = 0; oc < 16; oc++) s_red[warp*16 + oc] = t[oc];
    }
    __syncthreads();
    if (tid < 16) {
        float s = 0.f;
        #pragma unroll
        for (int w8 = 0; w8 < 8; w8++) s += s_red[w8*16 + tid];
        g_part[(b*16 + tid)*16 + blockIdx.y*4 + blockIdx.x] = s;
    }
}

// -------- combined head coefficients: phi = (phi1+phi2+phi3)/3 --------------
__global__ void phi_kernel(const float* __restrict__ wf1, const float* __restrict__ bf1,
                           const float* __restrict__ wf2, const float* __restrict__ bf2,
                           const float* __restrict__ wf3, const float* __restrict__ bf3) {
    const int b = blockIdx.x;
    const int t = threadIdx.x;
    const int c = t >> 4, ch = t & 15;
    __shared__ float red[48];
    float S = 0.f;
    if (t < 48) {
        const float* part = &g_part[(b*16 + ch)*16];
        float m[16];
        float sum16 = 0.f;
        #pragma unroll
        for (int p = 0; p < 16; p++) {
            m[p] = part[p] * (1.0f / 1024.0f);
            sum16 += m[p];
            S = fmaf(m[p], wf3[c*256 + ch*16 + p], S);
        }
        S = fmaf(sum16 * (1.f / 16.f), wf1[c*16 + ch], S);
        #pragma unroll
        for (int i = 0; i < 2; i++)
            #pragma unroll
            for (int j = 0; j < 2; j++) {
                float f2v = 0.25f * (m[(2*i)*4 + 2*j] + m[(2*i)*4 + 2*j + 1] +
                                     m[(2*i+1)*4 + 2*j] + m[(2*i+1)*4 + 2*j + 1]);
                S = fmaf(f2v, wf2[c*64 + ch*4 + i*2 + j], S);
            }
        red[t] = S;
    }
    __syncthreads();
    if (t < 3) {
        float tot = bf1[t] + bf2[t] + bf3[t];
        #pragma unroll
        for (int i = 0; i < 16; i++) tot += red[t*16 + i];
        g_phi[b*3 + t] = tot * (1.f / 3.f);
    }
}

// -------- fused grayscale + horizontal 21-tap Gaussian (reflect-101) --------
__global__ void grayblurh_kernel(const float* __restrict__ x, float* __restrict__ out) {
    __shared__ float row[256];
    __shared__ float sw[21];
    const int b = blockIdx.y, y = blockIdx.x;
    const int tx = threadIdx.x;
    if (tx < 21) {
        float t = (float)tx - 10.f;
        sw[tx] = expf(-(t * t) / 24.5f);
    }
    const float p0 = g_phi[b*3 + 0], p1 = g_phi[b*3 + 1], p2 = g_phi[b*3 + 2];
    const int i = y * 256 + tx;
    float v = p0 * x[(b*3 + 0)*NPIX0 + i]
            + p1 * x[(b*3 + 1)*NPIX0 + i]
            + p2 * x[(b*3 + 2)*NPIX0 + i];
    out[(b*3 + 1)*NPIX0 + i] = v;   // i_gray (channel 1)
    row[tx] = v;
    __syncthreads();
    float wsum = 0.f;
    #pragma unroll
    for (int t = 0; t < 21; t++) wsum += sw[t];
    float acc = 0.f;
    #pragma unroll
    for (int t = 0; t < 21; t++) {
        int xx = tx + t - 10;
        xx = xx < 0 ? -xx : (xx > 255 ? 510 - xx : xx);
        acc = fmaf(sw[t], row[xx], acc);
    }
    g_tmp[(b*256 + y)*256 + tx] = acc / wsum;
}

// -------- vertical 21-tap Gaussian + base/detail writes ---------------------
__global__ void blurv_kernel(float* __restrict__ out) {
    __shared__ float tile[84][32];
    __shared__ float sw[21];
    const int b = blockIdx.z;
    const int x0 = blockIdx.x * 32, y0 = blockIdx.y * 64;
    const int tid = threadIdx.y * 32 + threadIdx.x;
    if (tid < 21) {
        float t = (float)tid - 10.f;
        sw[tid] = expf(-(t * t) / 24.5f);
    }
    for (int i = tid; i < 84 * 32; i += 256) {
        int yy = i >> 5, xx = i & 31;
        int gy = y0 + yy - 10;
        gy = gy < 0 ? -gy : (gy > 255 ? 510 - gy : gy);
        tile[yy][xx] = g_tmp[(b*256 + gy)*256 + x0 + xx];
    }
    __syncthreads();
    float wsum = 0.f;
    #pragma unroll
    for (int t = 0; t < 21; t++) wsum += sw[t];
    const float inv = 1.f / wsum;
    const int tx = threadIdx.x;
    for (int r = 0; r < 8; r++) {
        const int ly = threadIdx.y * 8 + r;
        float acc = 0.f;
        #pragma unroll
        for (int t = 0; t < 21; t++) acc = fmaf(sw[t], tile[ly + t][tx], acc);
        const float base = acc * inv;
        const int gy = y0 + ly, gx = x0 + tx;
        const int idx = (b*3)*NPIX0 + gy*256 + gx;
        const float ig = out[idx + NPIX0];
        out[idx] = base;                  // base   (channel 0)
        out[idx + 2*NPIX0] = ig - base;   // detail (channel 2)
    }
}

// ---------------------------------------------------------------------------
extern "C" void kernel_launch(void* const* d_in, const int* in_sizes, int n_in,
                              void* d_out, int out_size) {
    const float* x   = (const float*)d_in[0];
    const float* w1  = (const float*)d_in[1];
    const float* b1  = (const float*)d_in[2];
    const float* w2  = (const float*)d_in[3];
    const float* b2  = (const float*)d_in[4];
    const float* w3  = (const float*)d_in[5];
    const float* b3  = (const float*)d_in[6];
    const float* wd  = (const float*)d_in[7];
    const float* bd  = (const float*)d_in[8];
    const float* wp  = (const float*)d_in[9];
    const float* bp  = (const float*)d_in[10];
    const float* wf1 = (const float*)d_in[11];
    const float* bf1 = (const float*)d_in[12];
    const float* wf2 = (const float*)d_in[13];
    const float* bf2 = (const float*)d_in[14];
    const float* wf3 = (const float*)d_in[15];
    const float* bf3 = (const float*)d_in[16];
    float* out = (float*)d_out;

    const int c12_smem = C12_SMEM_FLOATS * (int)sizeof(float);
    const int c3_smem  = C3_SMEM_FLOATS  * (int)sizeof(float);
    const int dw_smem  = DW_SMEM_FLOATS  * (int)sizeof(float);
    cudaFuncSetAttribute(conv12_kernel, cudaFuncAttributeMaxDynamicSharedMemorySize, c12_smem);
    cudaFuncSetAttribute(conv3_kernel,  cudaFuncAttributeMaxDynamicSharedMemorySize, c3_smem);
    cudaFuncSetAttribute(dwpw_kernel,   cudaFuncAttributeMaxDynamicSharedMemorySize, dw_smem);

    conv12_kernel<<<dim3(8, 8, BATCH), dim3(16, 16), c12_smem>>>(x, w1, b1, w2, b2);
    conv3_kernel<<<dim3(4, 4, BATCH), dim3(16, 16), c3_smem>>>(w3, b3);
    dwpw_kernel<<<dim3(4, 4, BATCH), dim3(16, 16), dw_smem>>>(wd, bd, wp, bp);
    phi_kernel<<<BATCH, 64>>>(wf1, bf1, wf2, bf2, wf3, bf3);
    grayblurh_kernel<<<dim3(256, BATCH), 256>>>(x, out);
    blurv_kernel<<<dim3(8, 4, BATCH), dim3(32, 8)>>>(out);
}